// round 8
// baseline (speedup 1.0000x reference)
#include <cuda_runtime.h>
#include <cuda_fp16.h>
#include <cstdint>

#define NC   3144   // counties
#define TT   156    // time steps
#define TP   154    // predicted steps (T - p)
#define TPAD 160    // padded t dimension
#define NCELL 40    // TPAD/4 uint4 (fp16) cells per column
#define NJ   80     // TPAD/2 float4 base cells per column
#define NNZ  31440
#define CAP  128    // bucket capacity (Poisson(10), max ~35)
#define FIXN 16     // staged nnz slots per column (P[cnt>16] ~ 2.7%)

#define SCAT_BLOCKS 123                 // ceil(NNZ/256)
#define COV_BLOCKS  13                  // ceil(NC/256)
#define NMB         50                  // ceil(NC/64)
#define NTC         10                  // TPAD/16
#define PREP_BLOCKS (NMB * NTC)         // 500

// ---- scratch (zero-initialized at load; meta slots >= cnt stay zero) ----
__device__ int    g_count[NC];
__device__ int4   g_meta[NC * CAP];     // {row, bv, av, hv}; pad slots = 0
__device__ float2 g_covb[NC];           // {ups@cov, zeta@cov}
__device__ uint4  g_csdh[NC * NCELL];   // 4x half2{cs,ds} per cell (4 t)
__device__ float4 g_base4[NC * NJ];     // {bc,bd,bc,bd} per 2 t

__device__ __forceinline__ unsigned int smem_u32(const void* p) {
    return (unsigned int)__cvta_generic_to_shared(p);
}

// ============================================================
// Kernel A: scatter (123) + cov (13) + prep (500) blocks.
// Prep: block = 64 counties x 16 t; thread = 1 county x 4 t.
// ============================================================
__global__ void prep_scatter_kernel(
    const float* __restrict__ C, const float* __restrict__ D,
    const float* __restrict__ M, const float* __restrict__ cov,
    const float* __restrict__ mu, const float* __restrict__ nu,
    const float* __restrict__ ups, const float* __restrict__ zeta,
    const float* __restrict__ bnz, const float* __restrict__ anz,
    const float* __restrict__ hnz, const int* __restrict__ rows,
    const int* __restrict__ cols)
{
    const int b  = blockIdx.x;
    const int tx = threadIdx.x;

    // ---------------- scatter ----------------
    if (b < SCAT_BLOCKS) {
        int k = b * 256 + tx;
        if (k < NNZ) {
            int c = cols[k];
            int slot = atomicAdd(&g_count[c], 1);
            if (slot < CAP)
                g_meta[c * CAP + slot] = make_int4(
                    rows[k], __float_as_int(bnz[k]),
                    __float_as_int(anz[k]), __float_as_int(hnz[k]));
        }
        return;
    }
    // ---------------- cov base ----------------
    if (b < SCAT_BLOCKS + COV_BLOCKS) {
        int m = (b - SCAT_BLOCKS) * 256 + tx;
        if (m < NC) {
            float a = 0.f, z = 0.f;
#pragma unroll
            for (int j = 0; j < 10; j++) {
                float cv = cov[j * NC + m];
                a += ups[j]  * cv;
                z += zeta[j] * cv;
            }
            g_covb[m] = make_float2(a, z);
        }
        return;
    }

    // ---------------- prep ----------------
    __shared__ uint4  s_h[64][4];       // fp16 csd cells
    __shared__ float4 s_b[64][8];       // base cells

    const int pb   = b - SCAT_BLOCKS - COV_BLOCKS;
    const int mblk = pb % NMB, tcb = pb / NMB;
    const int ml_  = tx & 63, sub = tx >> 6;
    const int m0   = mblk * 64;
    const int m    = min(m0 + ml_, NC - 1);
    const int t0   = tcb * 16 + sub * 4;

    float muv[12], nuv[12];
#pragma unroll
    for (int i = 0; i < 12; i++) { muv[i] = mu[i]; nuv[i] = nu[i]; }

    // rotating "next" values: each t-level loaded once per thread
    float cn = C[t0 * NC + m];
    float dn = D[t0 * NC + m];
    float mn[6];
#pragma unroll
    for (int k = 0; k < 6; k++) mn[k] = M[(k * TT + t0) * NC + m];

    float cs[4], ds[4], bc[4], bd[4];
#pragma unroll
    for (int j = 0; j < 4; j++) {
        int tn = min(t0 + j + 1, TT - 1);   // t>=154 never reaches output
        float c0 = cn;  cn = C[tn * NC + m];
        float d0 = dn;  dn = D[tn * NC + m];
        cs[j] = c0 + cn;
        ds[j] = d0 + dn;
        float mc = 0.f, md = 0.f;
#pragma unroll
        for (int k = 0; k < 6; k++) {
            float v0 = mn[k];
            float v1 = M[(k * TT + tn) * NC + m];
            mn[k] = v1;
            mc += muv[k*2] * v0 + muv[k*2+1] * v1;
            md += nuv[k*2] * v0 + nuv[k*2+1] * v1;
        }
        bc[j] = mc;
        bd[j] = md;
    }

    uint4 cellh;
    __half2* hp = reinterpret_cast<__half2*>(&cellh);
#pragma unroll
    for (int j = 0; j < 4; j++) hp[j] = __floats2half2_rn(cs[j], ds[j]);
    s_h[ml_][sub] = cellh;
    s_b[ml_][sub * 2    ] = make_float4(bc[0], bd[0], bc[1], bd[1]);
    s_b[ml_][sub * 2 + 1] = make_float4(bc[2], bd[2], bc[3], bd[3]);
    __syncthreads();

    // coalesced writeout: 64B runs (csdh), 128B runs (base)
    {
        int ml = tx >> 2, sl = tx & 3;
        if (m0 + ml < NC)
            g_csdh[(m0 + ml) * NCELL + tcb * 4 + sl] = s_h[ml][sl];
    }
#pragma unroll
    for (int i = 0; i < 2; i++) {
        int idx = i * 256 + tx;            // 0..511
        int ml = idx >> 3, cl = idx & 7;
        if (m0 + ml < NC)
            g_base4[(m0 + ml) * NJ + tcb * 8 + cl] = s_b[ml][cl];
    }
}

// ============================================================
// Kernel B: gather via cp.async staging. 786 blocks x 160 thr.
// Thread = one (column, 4t-cell). All <=16 nnz gathers of the
// block issued async into smem (one latency exposure), then
// FMA from smem. fp16 operand, fp32 accumulate.
// ============================================================
__global__ void __launch_bounds__(160) main_kernel(float* __restrict__ out)
{
    __shared__ __align__(16) uint4 gbuf[4 * FIXN * NCELL];   // 40 KB
    __shared__ int4 smeta[4][FIXN];
    __shared__ int  scnt[4];

    const int tid  = threadIdx.x;
    const int m0   = blockIdx.x * 4;      // NC = 786*4 exact
    const int col  = tid / NCELL;         // 0..3
    const int cell = tid - col * NCELL;   // 0..39
    const int m    = m0 + col;

    if (tid < 4 * FIXN)                   // warps 0-1: stage meta
        smeta[tid >> 4][tid & (FIXN - 1)] =
            g_meta[(m0 + (tid >> 4)) * CAP + (tid & (FIXN - 1))];
    if (tid >= 64 && tid < 68) {          // warp 2: counts + re-arm
        int c = tid - 64;
        scnt[c] = g_count[m0 + c];
        g_count[m0 + c] = 0;
    }
    __syncthreads();

    const int cnt = scnt[col];
    const int jn  = min(cnt, FIXN);

    // issue all gathers async: thread copies its own 16B cell per nnz
    const unsigned int dst0 = smem_u32(&gbuf[col * FIXN * NCELL + cell]);
    for (int j = 0; j < jn; j++) {
        const uint4* src = &g_csdh[smeta[col][j].x * NCELL + cell];
        asm volatile("cp.async.cg.shared.global [%0], [%1], 16;"
                     :: "r"(dst0 + (unsigned int)(j * NCELL * 16)), "l"(src));
    }
    asm volatile("cp.async.commit_group;");

    // overlap the drain with base + covariate loads
    const float2 cv = g_covb[m];
    const float4 b0 = g_base4[m * NJ + 2 * cell];
    const float4 b1 = g_base4[m * NJ + 2 * cell + 1];
    float accC[4], accD[4];
    accC[0] = b0.x + cv.x;  accD[0] = b0.y + cv.y;
    accC[1] = b0.z + cv.x;  accD[1] = b0.w + cv.y;
    accC[2] = b1.x + cv.x;  accD[2] = b1.y + cv.y;
    accC[3] = b1.z + cv.x;  accD[3] = b1.w + cv.y;

    asm volatile("cp.async.wait_group 0;" ::: "memory");
    // no barrier needed: each thread reads only cells it copied itself

    const uint4* __restrict__ myg = &gbuf[col * FIXN * NCELL + cell];
#pragma unroll 4
    for (int j = 0; j < jn; j++) {
        int4  md = smeta[col][j];
        uint4 v  = myg[j * NCELL];
        float bv = __int_as_float(md.y);
        float av = __int_as_float(md.z);
        float hv = __int_as_float(md.w);
        const __half2* h = reinterpret_cast<const __half2*>(&v);
#pragma unroll
        for (int k = 0; k < 4; k++) {
            float2 p = __half22float2(h[k]);
            accC[k] += bv * p.x;
            accD[k] += hv * p.x + av * p.y;
        }
    }
    // rare tail (cnt > FIXN, ~3% of columns): direct gather
    for (int s = FIXN; s < cnt; s++) {
        int4  md = g_meta[m * CAP + s];
        uint4 v  = g_csdh[md.x * NCELL + cell];
        float bv = __int_as_float(md.y);
        float av = __int_as_float(md.z);
        float hv = __int_as_float(md.w);
        const __half2* h = reinterpret_cast<const __half2*>(&v);
#pragma unroll
        for (int k = 0; k < 4; k++) {
            float2 p = __half22float2(h[k]);
            accC[k] += bv * p.x;
            accD[k] += hv * p.x + av * p.y;
        }
    }

    __syncthreads();                      // all gbuf reads done; alias as tile
    float2* tile = reinterpret_cast<float2*>(gbuf);   // [TPAD][5] padded
#pragma unroll
    for (int k = 0; k < 4; k++)
        tile[(4 * cell + k) * 5 + col] = make_float2(accC[k], accD[k]);
    __syncthreads();

#pragma unroll
    for (int i = 0; i < 4; i++) {
        int idx = i * 160 + tid;          // < 640 = TPAD*4
        int t = idx >> 2, mo = idx & 3;
        if (t < TP) {
            float2 v = tile[t * 5 + mo];
            out[t        * NC + m0 + mo] = v.x;
            out[(TP + t) * NC + m0 + mo] = v.y;
        }
    }
}

// ============================================================
extern "C" void kernel_launch(void* const* d_in, const int* in_sizes, int n_in,
                              void* d_out, int out_size)
{
    const float* C    = (const float*)d_in[0];
    const float* D    = (const float*)d_in[1];
    const float* M    = (const float*)d_in[2];
    const float* cov  = (const float*)d_in[3];
    const float* bnz  = (const float*)d_in[4];
    const float* anz  = (const float*)d_in[5];
    const float* hnz  = (const float*)d_in[6];
    const float* mu   = (const float*)d_in[7];
    const float* nu   = (const float*)d_in[8];
    const float* ups  = (const float*)d_in[9];
    const float* zeta = (const float*)d_in[10];
    const int*   rows = (const int*)d_in[11];
    const int*   cols = (const int*)d_in[12];
    float* out = (float*)d_out;

    prep_scatter_kernel<<<SCAT_BLOCKS + COV_BLOCKS + PREP_BLOCKS, 256>>>(
        C, D, M, cov, mu, nu, ups, zeta, bnz, anz, hnz, rows, cols);

    main_kernel<<<NC / 4, 160>>>(out);
}

// round 9
// speedup vs baseline: 1.0621x; 1.0621x over previous
#include <cuda_runtime.h>
#include <cuda_fp16.h>
#include <cstdint>

#define NC   3144   // counties
#define TT   156    // time steps
#define TP   154    // predicted steps (T - p)
#define TPAD 160    // padded t dimension
#define NNZ  31440
#define CAP  128    // bucket capacity (Poisson(10), max ~35)
#define FIXN 16     // staged nnz slots (P[cnt>16] ~ 2.7%, tail handled)

#define NMT  99     // m-tiles of 32 (99*32 = 3168 >= 3144)
#define NTT  5      // t-tiles of 32 (cover TPAD)

#define SCAT_BLOCKS  31   // ceil(NNZ/1024)
#define COV_BLOCKS   4    // ceil(NC/1024)
#define TRANS_BLOCKS (NMT * NTT)   // 495

// ---- scratch (zero-initialized at load; meta slots >= cnt stay zero) ----
__device__ int     g_count[NC];
__device__ int     g_done[NMT];       // arrival counters for count re-arm
__device__ int4    g_meta[NC * CAP];  // {row, bv, av, hv}; pad slots = 0
__device__ float2  g_covb[NC];        // {ups@cov, zeta@cov}
__device__ __half2 g_csdh[NC * TPAD]; // {cs, ds} fp16 at [m][t]

// ============================================================
// Kernel A (1024 thr): scatter (31) + covb (4) + C/D lag-sum
// transpose (495 blocks, 32m x 32t tiles -> fp16 [m][t]).
// ============================================================
__global__ void prep_kernel(
    const float* __restrict__ C, const float* __restrict__ D,
    const float* __restrict__ cov,
    const float* __restrict__ ups, const float* __restrict__ zeta,
    const float* __restrict__ bnz, const float* __restrict__ anz,
    const float* __restrict__ hnz, const int* __restrict__ rows,
    const int* __restrict__ cols)
{
    const int b = blockIdx.x, tid = threadIdx.x;

    if (b < SCAT_BLOCKS) {
        int k = b * 1024 + tid;
        if (k < NNZ) {
            int c = cols[k];
            int slot = atomicAdd(&g_count[c], 1);
            if (slot < CAP)
                g_meta[c * CAP + slot] = make_int4(
                    rows[k], __float_as_int(bnz[k]),
                    __float_as_int(anz[k]), __float_as_int(hnz[k]));
        }
        return;
    }
    if (b < SCAT_BLOCKS + COV_BLOCKS) {
        int m = (b - SCAT_BLOCKS) * 1024 + tid;
        if (m < NC) {
            float a = 0.f, z = 0.f;
#pragma unroll
            for (int j = 0; j < 10; j++) {
                float cvv = cov[j * NC + m];
                a += ups[j]  * cvv;
                z += zeta[j] * cvv;
            }
            g_covb[m] = make_float2(a, z);
        }
        return;
    }

    // ---- transpose tile: rows t0..t0+32 (33), cols m0..m0+31 ----
    __shared__ float sC[33][33], sD[33][33];
    const int tb2 = b - SCAT_BLOCKS - COV_BLOCKS;
    const int m0 = (tb2 % NMT) * 32, t0 = (tb2 / NMT) * 32;

    for (int idx = tid; idx < 33 * 32; idx += 1024) {
        int r = idx >> 5, cm = idx & 31;
        int tg = min(t0 + r, TT - 1);
        int mg = min(m0 + cm, NC - 1);
        sC[r][cm] = C[tg * NC + mg];
        sD[r][cm] = D[tg * NC + mg];
    }
    __syncthreads();

    const int tx = tid & 31, ty = tid >> 5;   // tx = t offset, ty = m offset
    const int mg = m0 + ty;
    if (mg < NC) {
        float cs = sC[tx][ty] + sC[tx + 1][ty];
        float ds = sD[tx][ty] + sD[tx + 1][ty];
        g_csdh[mg * TPAD + t0 + tx] = __floats2half2_rn(cs, ds);
    }
}

// ============================================================
// Kernel B (256 thr, grid (99, 5)): fused base + gather + out.
// Tile = 32 t x 32 m, accumulated in smem.
//  phase 1: mobility base from M (lanes along m, coalesced)
//  phase 2: sparse gather (warp per column, lanes along t)
//  phase 3: native-layout coalesced output
// ============================================================
__global__ void __launch_bounds__(256) main_kernel(
    float* __restrict__ out, const float* __restrict__ M,
    const float* __restrict__ mu, const float* __restrict__ nu)
{
    __shared__ float accC[32][33], accD[32][33];   // [t_local][m_local]
    __shared__ int4  smeta[32][FIXN];              // 8 KB
    __shared__ int   scnt[32];

    const int tid  = threadIdx.x;
    const int w    = tid >> 5, lane = tid & 31;
    const int m0   = blockIdx.x * 32;
    const int tb   = blockIdx.y * 32;

    // ---- stage meta + counts (coalesced) ----
#pragma unroll
    for (int i = 0; i < 2; i++) {
        int idx = i * 256 + tid;          // 512 = 32 cols x 16 slots
        int c = idx >> 4, s = idx & 15;
        if (m0 + c < NC)
            smeta[c][s] = g_meta[(m0 + c) * CAP + s];
    }
    if (tid < 32)
        scnt[tid] = (m0 + tid < NC) ? g_count[m0 + tid] : 0;

    // ---- phase 1: mobility + covariate base (lanes along m) ----
    const int mg = m0 + lane;
    const int m  = min(mg, NC - 1);
    const int tr0 = tb + 4 * w;           // this warp owns t rows tr0..tr0+3
    float2 cv = g_covb[m];
    float mc[4], md[4];
#pragma unroll
    for (int j = 0; j < 4; j++) { mc[j] = cv.x; md[j] = cv.y; }

#pragma unroll
    for (int k = 0; k < 6; k++) {
        float m2a = mu[2 * k], m2b = mu[2 * k + 1];
        float n2a = nu[2 * k], n2b = nu[2 * k + 1];
        float mv = M[(k * TT + min(tr0, TT - 1)) * NC + m];
#pragma unroll
        for (int j = 0; j < 4; j++) {
            int tn = min(tr0 + j + 1, TT - 1);
            float v1 = M[(k * TT + tn) * NC + m];
            mc[j] += m2a * mv + m2b * v1;
            md[j] += n2a * mv + n2b * v1;
            mv = v1;
        }
    }
#pragma unroll
    for (int j = 0; j < 4; j++) {
        accC[4 * w + j][lane] = mc[j];
        accD[4 * w + j][lane] = md[j];
    }
    __syncthreads();

    // count re-arm: last of the 5 t-tile blocks zeroes this m-group
    if (tid == 0) {
        __threadfence();
        int old = atomicAdd(&g_done[blockIdx.x], 1);
        if (old == NTT - 1) {
            g_done[blockIdx.x] = 0;
            for (int c = 0; c < 32 && m0 + c < NC; c++) g_count[m0 + c] = 0;
        }
    }

    // ---- phase 2: sparse gather (warp per column, lanes = t) ----
#pragma unroll
    for (int cc = 0; cc < 4; cc++) {
        const int c = w + 8 * cc;         // column owned by this warp
        const int cnt = scnt[c];
        const int jn = min(cnt, FIXN);
        float rc = 0.f, rd = 0.f;
        for (int j = 0; j < jn; j++) {
            int4 mdta = smeta[c][j];      // LDS broadcast
            float2 p = __half22float2(g_csdh[mdta.x * TPAD + tb + lane]);
            rc += __int_as_float(mdta.y) * p.x;
            rd += __int_as_float(mdta.w) * p.x + __int_as_float(mdta.z) * p.y;
        }
        for (int s = FIXN; s < cnt; s++) {  // rare tail
            int4 mdta = g_meta[(m0 + c) * CAP + s];
            float2 p = __half22float2(g_csdh[mdta.x * TPAD + tb + lane]);
            rc += __int_as_float(mdta.y) * p.x;
            rd += __int_as_float(mdta.w) * p.x + __int_as_float(mdta.z) * p.y;
        }
        accC[lane][c] += rc;              // conflict-free RMW (stride 33)
        accD[lane][c] += rd;
    }
    __syncthreads();

    // ---- phase 3: native-layout coalesced output ----
#pragma unroll
    for (int j = 0; j < 4; j++) {
        int tr = 4 * w + j;
        int t  = tb + tr;
        if (t < TP && mg < NC) {
            out[t        * NC + mg] = accC[tr][lane];
            out[(TP + t) * NC + mg] = accD[tr][lane];
        }
    }
}

// ============================================================
extern "C" void kernel_launch(void* const* d_in, const int* in_sizes, int n_in,
                              void* d_out, int out_size)
{
    const float* C    = (const float*)d_in[0];
    const float* D    = (const float*)d_in[1];
    const float* M    = (const float*)d_in[2];
    const float* cov  = (const float*)d_in[3];
    const float* bnz  = (const float*)d_in[4];
    const float* anz  = (const float*)d_in[5];
    const float* hnz  = (const float*)d_in[6];
    const float* mu   = (const float*)d_in[7];
    const float* nu   = (const float*)d_in[8];
    const float* ups  = (const float*)d_in[9];
    const float* zeta = (const float*)d_in[10];
    const int*   rows = (const int*)d_in[11];
    const int*   cols = (const int*)d_in[12];
    float* out = (float*)d_out;

    prep_kernel<<<SCAT_BLOCKS + COV_BLOCKS + TRANS_BLOCKS, 1024>>>(
        C, D, cov, ups, zeta, bnz, anz, hnz, rows, cols);

    main_kernel<<<dim3(NMT, NTT), 256>>>(out, M, mu, nu);
}